// round 1
// baseline (speedup 1.0000x reference)
#include <cuda_runtime.h>

// Problem constants
#define S_LEN 2048
#define B_SZ 4
#define HID 2048
#define T_TOK 8192          // B_SZ * S_LEN
#define FF 1408
#define FF2 2816
#define NEXP 8
#define NROWS 16384         // T_TOK * TOP_K (always exact: every token -> 2 experts)

// ---------------- scratch (device globals; no runtime allocation) ----------------
__device__ int   d_counts[NEXP];
__device__ int   d_offsets[NEXP + 1];
__device__ int   d_cursor[NEXP];
__device__ int   d_ea[T_TOK];
__device__ int   d_eb[T_TOK];
__device__ float d_wa[T_TOK];
__device__ float d_wb[T_TOK];
__device__ int   d_row_token[NROWS];
__device__ int   d_token_pos[T_TOK * 2];
__device__ float d_h[(size_t)NROWS * FF2];   // 184 MB: h = Xg @ w1e
__device__ float d_g[(size_t)NROWS * FF];    //  92 MB: swiglu(h)
__device__ float d_y[(size_t)NROWS * HID];   // 134 MB: y = g @ w2e

// ---------------- tiny init ----------------
__global__ void zero_counts_kernel() {
    if (threadIdx.x < NEXP) d_counts[threadIdx.x] = 0;
}

// ---------------- gate: logits -> softmax -> top2 -> normalized weights ----------------
__global__ void gate_kernel(const float* __restrict__ x, const float* __restrict__ wg) {
    int t = blockIdx.x;
    // xt[t] = x[s, b, :] with t = b*S + s
    const float* xr = x + ((size_t)(t % S_LEN) * B_SZ + (t / S_LEN)) * HID;

    float acc[NEXP];
#pragma unroll
    for (int e = 0; e < NEXP; e++) acc[e] = 0.f;

    for (int h = threadIdx.x; h < HID; h += 256) {
        float xv = xr[h];
#pragma unroll
        for (int e = 0; e < NEXP; e++) acc[e] += xv * wg[e * HID + h];
    }
#pragma unroll
    for (int e = 0; e < NEXP; e++)
        for (int off = 16; off; off >>= 1)
            acc[e] += __shfl_down_sync(0xffffffffu, acc[e], off);

    __shared__ float red[8][NEXP];
    int warp = threadIdx.x >> 5, lane = threadIdx.x & 31;
    if (lane == 0) {
#pragma unroll
        for (int e = 0; e < NEXP; e++) red[warp][e] = acc[e];
    }
    __syncthreads();

    if (threadIdx.x == 0) {
        float logits[NEXP];
#pragma unroll
        for (int e = 0; e < NEXP; e++) {
            float s = 0.f;
            for (int w = 0; w < 8; w++) s += red[w][e];
            logits[e] = s;
        }
        float m = logits[0];
#pragma unroll
        for (int e = 1; e < NEXP; e++) m = fmaxf(m, logits[e]);
        float sc[NEXP];
        float Z = 0.f;
#pragma unroll
        for (int e = 0; e < NEXP; e++) { sc[e] = expf(logits[e] - m); Z += sc[e]; }
        float invZ = 1.f / Z;
#pragma unroll
        for (int e = 0; e < NEXP; e++) sc[e] *= invZ;

        // top-2, stable (first occurrence wins ties, matching lax.top_k)
        int e0 = 0;
#pragma unroll
        for (int e = 1; e < NEXP; e++) if (sc[e] > sc[e0]) e0 = e;
        int e1 = (e0 == 0) ? 1 : 0;
#pragma unroll
        for (int e = 0; e < NEXP; e++) if (e != e0 && sc[e] > sc[e1]) e1 = e;

        float s0 = sc[e0], s1 = sc[e1];
        float inv = 1.f / (s0 + s1 + 1e-20f);
        d_ea[t] = e0; d_eb[t] = e1;
        d_wa[t] = s0 * inv; d_wb[t] = s1 * inv;
        atomicAdd(&d_counts[e0], 1);
        atomicAdd(&d_counts[e1], 1);
    }
}

// ---------------- exclusive scan over 8 experts ----------------
__global__ void scan_kernel() {
    int o = 0;
    d_offsets[0] = 0;
#pragma unroll
    for (int e = 0; e < NEXP; e++) {
        o += d_counts[e];
        d_offsets[e + 1] = o;
        // cursor init
    }
#pragma unroll
    for (int e = 0; e < NEXP; e++) d_cursor[e] = d_offsets[e];
}

// ---------------- scatter: token -> permuted row slots ----------------
__global__ void assign_kernel() {
    int t = blockIdx.x * blockDim.x + threadIdx.x;
    if (t >= T_TOK) return;
    int p0 = atomicAdd(&d_cursor[d_ea[t]], 1);
    d_row_token[p0] = t;
    d_token_pos[2 * t] = p0;
    int p1 = atomicAdd(&d_cursor[d_eb[t]], 1);
    d_row_token[p1] = t;
    d_token_pos[2 * t + 1] = p1;
}

// ---------------- segment-aware tiled SGEMM ----------------
// MODE 0: C=d_h = gather(x) @ w1e   (K=HID,  N=FF2)
// MODE 1: C=d_y = d_g      @ w2e    (K=FF,   N=HID)
// 128x128 tile, BK=8, 256 threads, 8x8 per-thread micro-tile.
template <int MODE>
__global__ void __launch_bounds__(256, 2)
gemm_kernel(const float* __restrict__ Xin, const float* __restrict__ Wbase) {
    constexpr int Kd = (MODE == 0) ? HID : FF;
    constexpr int Nd = (MODE == 0) ? FF2 : HID;
    float* __restrict__ C = (MODE == 0) ? d_h : d_y;

    int e = blockIdx.z;
    int seg0 = d_offsets[e], seg1 = d_offsets[e + 1];
    int row0 = seg0 + blockIdx.x * 128;
    if (row0 >= seg1) return;
    int col0 = blockIdx.y * 128;

    const float* W = Wbase + (size_t)e * Kd * Nd + col0;

    __shared__ float As[8][128];
    __shared__ float Bs[8][128];

    int tid = threadIdx.x;

    // A-tile load mapping: 128 rows x 8 k, one float4 per thread
    int a_row = tid >> 1;
    int a_col = (tid & 1) * 4;
    int grow = row0 + a_row;
    bool a_valid = grow < seg1;
    const float* Arow;
    if (MODE == 0) {
        int t = a_valid ? d_row_token[grow] : 0;
        Arow = Xin + ((size_t)(t % S_LEN) * B_SZ + (t / S_LEN)) * HID;
    } else {
        Arow = d_g + (size_t)(a_valid ? grow : 0) * Kd;
    }

    // B-tile load mapping: 8 k-rows x 128 cols, one float4 per thread
    int b_row = tid >> 5;
    int b_col = (tid & 31) * 4;
    const float* Wp = W + (size_t)b_row * Nd + b_col;

    float acc[8][8];
#pragma unroll
    for (int i = 0; i < 8; i++)
#pragma unroll
        for (int j = 0; j < 8; j++) acc[i][j] = 0.f;

    int ty = tid >> 4, tx = tid & 15;

    for (int k0 = 0; k0 < Kd; k0 += 8) {
        float4 av = a_valid ? *(const float4*)(Arow + k0 + a_col)
                            : make_float4(0.f, 0.f, 0.f, 0.f);
        As[a_col + 0][a_row] = av.x;
        As[a_col + 1][a_row] = av.y;
        As[a_col + 2][a_row] = av.z;
        As[a_col + 3][a_row] = av.w;
        *(float4*)&Bs[b_row][b_col] = *(const float4*)(Wp + (size_t)k0 * Nd);
        __syncthreads();
#pragma unroll
        for (int k = 0; k < 8; k++) {
            float a[8], b[8];
#pragma unroll
            for (int i = 0; i < 8; i++) a[i] = As[k][ty * 8 + i];
#pragma unroll
            for (int j = 0; j < 8; j++) b[j] = Bs[k][tx * 8 + j];
#pragma unroll
            for (int i = 0; i < 8; i++)
#pragma unroll
                for (int j = 0; j < 8; j++) acc[i][j] += a[i] * b[j];
        }
        __syncthreads();
    }

#pragma unroll
    for (int i = 0; i < 8; i++) {
        int gr = row0 + ty * 8 + i;
        if (gr < seg1) {
            float* cp = C + (size_t)gr * Nd + col0 + tx * 8;
            *(float4*)cp = make_float4(acc[i][0], acc[i][1], acc[i][2], acc[i][3]);
            *(float4*)(cp + 4) = make_float4(acc[i][4], acc[i][5], acc[i][6], acc[i][7]);
        }
    }
}

// ---------------- swiglu: g = silu(h[:, :F]) * h[:, F:] ----------------
__global__ void swiglu_kernel() {
    int idx = blockIdx.x * blockDim.x + threadIdx.x;
    const int total = NROWS * (FF / 4);
    if (idx >= total) return;
    int r = idx / (FF / 4);
    int j4 = idx % (FF / 4);
    const float4 a = *(const float4*)&d_h[(size_t)r * FF2 + j4 * 4];
    const float4 b = *(const float4*)&d_h[(size_t)r * FF2 + FF + j4 * 4];
    float4 o;
    o.x = (a.x / (1.f + expf(-a.x))) * b.x;
    o.y = (a.y / (1.f + expf(-a.y))) * b.y;
    o.z = (a.z / (1.f + expf(-a.z))) * b.z;
    o.w = (a.w / (1.f + expf(-a.w))) * b.w;
    *(float4*)&d_g[(size_t)r * FF + j4 * 4] = o;
}

// ---------------- combine: out[s,b,:] = wa*y[pos0] + wb*y[pos1] ----------------
__global__ void combine_kernel(float* __restrict__ out) {
    int v = blockIdx.x * blockDim.x + threadIdx.x;
    const int total = T_TOK * (HID / 4);
    if (v >= total) return;
    int t = v / (HID / 4);
    int h4 = v % (HID / 4);
    int p0 = d_token_pos[2 * t], p1 = d_token_pos[2 * t + 1];
    float wa = d_wa[t], wb = d_wb[t];
    const float4 y0 = *(const float4*)&d_y[(size_t)p0 * HID + h4 * 4];
    const float4 y1 = *(const float4*)&d_y[(size_t)p1 * HID + h4 * 4];
    float4 o;
    o.x = wa * y0.x + wb * y1.x;
    o.y = wa * y0.y + wb * y1.y;
    o.z = wa * y0.z + wb * y1.z;
    o.w = wa * y0.w + wb * y1.w;
    int s = t % S_LEN, b = t / S_LEN;
    *(float4*)&out[((size_t)s * B_SZ + b) * HID + h4 * 4] = o;
}

// ---------------- launch ----------------
extern "C" void kernel_launch(void* const* d_in, const int* in_sizes, int n_in,
                              void* d_out, int out_size) {
    const float* x  = (const float*)d_in[0];
    const float* wg = (const float*)d_in[1];
    const float* w1 = (const float*)d_in[2];
    const float* w2 = (const float*)d_in[3];
    float* out = (float*)d_out;

    zero_counts_kernel<<<1, 32>>>();
    gate_kernel<<<T_TOK, 256>>>(x, wg);
    scan_kernel<<<1, 1>>>();
    assign_kernel<<<T_TOK / 256, 256>>>();

    // gemm1: h = gather(x) @ w1e   -> d_h
    gemm_kernel<0><<<dim3(128, FF2 / 128, NEXP), 256>>>(x, w1);
    // swiglu -> d_g
    swiglu_kernel<<<(NROWS * (FF / 4)) / 256, 256>>>();
    // gemm2: y = g @ w2e -> d_y
    gemm_kernel<1><<<dim3(128, HID / 128, NEXP), 256>>>(nullptr, w2);
    // weighted combine -> out
    combine_kernel<<<(T_TOK * (HID / 4)) / 256, 256>>>(out);
}